// round 15
// baseline (speedup 1.0000x reference)
#include <cuda_runtime.h>

#define B_ 256
#define T_ 1024
#define K_ 128
#define FWD_BLOCKS_ 128
#define NBLOCKS_ (FWD_BLOCKS_ + B_)

__device__ float g_denom[B_];
__device__ float g_num[B_];
__device__ unsigned int g_count = 0;

typedef unsigned long long u64;

__device__ __forceinline__ void ffma2(u64 &d, u64 a, u64 b) {
    asm("fma.rn.f32x2 %0, %1, %2, %0;" : "+l"(d) : "l"(a), "l"(b));
}
__device__ __forceinline__ u64 fadd2(u64 a, u64 b) {
    u64 r; asm("add.rn.f32x2 %0, %1, %2;" : "=l"(r) : "l"(a), "l"(b)); return r;
}
__device__ __forceinline__ u64 pack2(float lo, float hi) {
    u64 r; asm("mov.b64 %0, {%1, %2};" : "=l"(r) : "f"(lo), "f"(hi)); return r;
}
__device__ __forceinline__ void unpack2(u64 v, float &lo, float &hi) {
    asm("mov.b64 {%0, %1}, %2;" : "=f"(lo), "=f"(hi) : "l"(v));
}

// ---------------------------------------------------------------------------
// Single launch:
//   blocks [0,128):   forward, TWO batches per block INTERLEAVED IN-THREAD
//                     (128 threads = one group; E registers shared by both
//                     batches since transitions are batch-invariant). The two
//                     matvec chains are independent -> when batch0's tree
//                     stalls (LDS latency, shfl), batch1's FMAs issue. ONE
//                     __syncthreads() per step serves both batches.
//   blocks [128,384): numerator, 1 batch/block (128 threads)
//   last block: ticket reduction -> out.
//
// Per-thread layout (proven R12 shape): states jA = w*16+(l&15), jB = jA+64,
// i-half h = l>>4; permuted p storage -> 1-wavefront broadcast LDS.128;
// halves combine via one packed shfl_xor(16). Per batch: 4-deep emission
// ring, rcp(p0) parallel to tree, log(p0) off-path.
// ---------------------------------------------------------------------------
__global__ void __launch_bounds__(128) fused_kernel(
    const float* inp, const float* trans, const int* tags, const int* mask,
    float* out) {
    const int tid = threadIdx.x;

    __shared__ __align__(16) float pbuf[2][2][K_];   // [batch][buffer][slot]
    __shared__ int smask[2][T_];
    __shared__ float sf[128];
    __shared__ int   si[128];
    __shared__ unsigned int s_rank;

    if (blockIdx.x < FWD_BLOCKS_) {
        // ================= forward: batches 2*bx, 2*bx+1 =================
        const int w   = tid >> 5;
        const int l   = tid & 31;
        const int h   = l >> 4;               // i-half
        const int jlo = w * 16 + (l & 15);
        const int jA = jlo, jB = jlo + 64;
        const int b0 = blockIdx.x * 2, b1 = b0 + 1;
        const int posA = ((jlo >> 2) << 3) | (jlo & 3);   // permuted slot

        for (int t = tid; t < T_; t += 128) {
            smask[0][t] = mask[(size_t)b0 * T_ + t];
            smask[1][t] = mask[(size_t)b1 * T_ + t];
        }

        // E columns (shared by both batches): 64 u64 = 128 regs.
        u64 EA[32], EB[32];
#pragma unroll
        for (int m = 0; m < 32; m++) {
            const int i = (h << 6) + 2 * m;
            EA[m] = pack2(__expf(trans[i * K_ + jA]),
                          __expf(trans[(i + 1) * K_ + jA]));
            EB[m] = pack2(__expf(trans[i * K_ + jB]),
                          __expf(trans[(i + 1) * K_ + jB]));
        }

        const float* eA0 = inp + (size_t)b0 * T_ * K_ + jA;
        const float* eB0 = inp + (size_t)b0 * T_ * K_ + jB;
        const float* eA1 = inp + (size_t)b1 * T_ * K_ + jA;
        const float* eB1 = inp + (size_t)b1 * T_ * K_ + jB;

        float pA0 = __expf(eA0[0]), pB0 = __expf(eB0[0]);   // t = 0
        float pA1 = __expf(eA1[0]), pB1 = __expf(eB1[0]);
        if (h == 0) {
            pbuf[0][0][posA] = pA0; pbuf[0][0][posA + 4] = pB0;
            pbuf[1][0][posA] = pA1; pbuf[1][0][posA + 4] = pB1;
        }
        float C0 = 0.0f, C1 = 0.0f;

        // emission rings (per batch): ee*, r1..r4
        float eeA0 = __expf(eA0[K_]), eeB0 = __expf(eB0[K_]);
        float eeA1 = __expf(eA1[K_]), eeB1 = __expf(eB1[K_]);
        float r1A0 = eA0[2*K_], r1B0 = eB0[2*K_], r1A1 = eA1[2*K_], r1B1 = eB1[2*K_];
        float r2A0 = eA0[3*K_], r2B0 = eB0[3*K_], r2A1 = eA1[3*K_], r2B1 = eB1[3*K_];
        float r3A0 = eA0[4*K_], r3B0 = eB0[4*K_], r3A1 = eA1[4*K_], r3B1 = eB1[4*K_];
        float r4A0 = eA0[5*K_], r4B0 = eB0[5*K_], r4A1 = eA1[5*K_], r4B1 = eB1[5*K_];
        __syncthreads();

        int cur = 0;
        for (int t = 1; t < T_; t++) {
            const int i5 = (t + 5 < T_) ? (t + 5) : (T_ - 1);
            const size_t o5 = (size_t)i5 << 7;
            const float rnA0 = eA0[o5], rnB0 = eB0[o5];
            const float rnA1 = eA1[o5], rnB1 = eB1[o5];
            const float xA0 = __expf(r1A0), xB0 = __expf(r1B0);
            const float xA1 = __expf(r1A1), xB1 = __expf(r1B1);
            const int mc0 = smask[0][t], mc1 = smask[1][t];

            const float q0  = pbuf[0][cur][0];
            const float q1  = pbuf[1][cur][0];
            const float rp0 = __frcp_rn(q0), rp1 = __frcp_rn(q1);
            const float lp0 = __logf(q0),   lp1 = __logf(q1);   // off-path

            const ulonglong2* pv0 = (const ulonglong2*)pbuf[0][cur] + h;
            const ulonglong2* pv1 = (const ulonglong2*)pbuf[1][cur] + h;

            // ---- batch 0 tree ----
            u64 aA0=0ULL, aA1_=0ULL, aB0=0ULL, aB1_=0ULL;
#pragma unroll
            for (int k = 0; k < 16; k++) {
                const ulonglong2 u = pv0[2 * k];
                ffma2(aA0,  u.x, EA[2*k]); ffma2(aA1_, u.y, EA[2*k+1]);
                ffma2(aB0,  u.x, EB[2*k]); ffma2(aB1_, u.y, EB[2*k+1]);
            }
            float lo0a, hi0a, lo0b, hi0b;
            unpack2(fadd2(aA0, aA1_), lo0a, hi0a);
            unpack2(fadd2(aB0, aB1_), lo0b, hi0b);
            u64 h0 = pack2(lo0a + hi0a, lo0b + hi0b);
            const u64 o0 = __shfl_xor_sync(0xffffffffu, h0, 16);
            float sA0v, sB0v; unpack2(fadd2(h0, o0), sA0v, sB0v);

            // ---- batch 1 tree (independent chain) ----
            u64 cA0=0ULL, cA1_=0ULL, cB0=0ULL, cB1_=0ULL;
#pragma unroll
            for (int k = 0; k < 16; k++) {
                const ulonglong2 u = pv1[2 * k];
                ffma2(cA0,  u.x, EA[2*k]); ffma2(cA1_, u.y, EA[2*k+1]);
                ffma2(cB0,  u.x, EB[2*k]); ffma2(cB1_, u.y, EB[2*k+1]);
            }
            float lo1a, hi1a, lo1b, hi1b;
            unpack2(fadd2(cA0, cA1_), lo1a, hi1a);
            unpack2(fadd2(cB0, cB1_), lo1b, hi1b);
            u64 h1 = pack2(lo1a + hi1a, lo1b + hi1b);
            const u64 o1 = __shfl_xor_sync(0xffffffffu, h1, 16);
            float sA1v, sB1v; unpack2(fadd2(h1, o1), sA1v, sB1v);

            // ---- updates ----
            const float nA0 = sA0v * (eeA0 * rp0), nB0 = sB0v * (eeB0 * rp0);
            const float nA1 = sA1v * (eeA1 * rp1), nB1 = sB1v * (eeB1 * rp1);
            const float wA0 = mc0 ? nA0 : pA0, wB0 = mc0 ? nB0 : pB0;
            const float wA1 = mc1 ? nA1 : pA1, wB1 = mc1 ? nB1 : pB1;
            C0 += mc0 ? lp0 : 0.0f;
            C1 += mc1 ? lp1 : 0.0f;

            cur ^= 1;
            if (h == 0) {
                pbuf[0][cur][posA] = wA0; pbuf[0][cur][posA + 4] = wB0;
                pbuf[1][cur][posA] = wA1; pbuf[1][cur][posA + 4] = wB1;
            }
            pA0 = wA0; pB0 = wB0; pA1 = wA1; pB1 = wB1;
            __syncthreads();                   // one barrier for both batches

            eeA0 = xA0; eeB0 = xB0; eeA1 = xA1; eeB1 = xB1;
            r1A0=r2A0; r2A0=r3A0; r3A0=r4A0; r4A0=rnA0;
            r1B0=r2B0; r2B0=r3B0; r3B0=r4B0; r4B0=rnB0;
            r1A1=r2A1; r2A1=r3A1; r3A1=r4A1; r4A1=rnA1;
            r1B1=r2B1; r2B1=r3B1; r3B1=r4B1; r4B1=rnB1;
        }

        if (tid == 0) {
            float s0 = 0.0f, s1 = 0.0f;        // fixed order: deterministic
            for (int i = 0; i < K_; i++) { s0 += pbuf[0][cur][i]; s1 += pbuf[1][cur][i]; }
            g_denom[b0] = C0 + __logf(s0);
            g_denom[b1] = C1 + __logf(s1);
            __threadfence();
        }
    } else {
        // ================= numerator =================
        const int b = blockIdx.x - FWD_BLOCKS_;   // 0..255
        const int*   tb = tags + (size_t)b * T_;
        const int*   mb = mask + (size_t)b * T_;
        const float* eb = inp  + (size_t)b * T_ * K_;

        float s = 0.0f;
        int msum = 0;
        for (int t = tid; t < T_; t += 128) {
            msum += mb[t];
            if (t < T_ - 1) {
                const int tg  = tb[t]     & (K_ - 1);
                const int tg1 = tb[t + 1] & (K_ - 1);
                s += trans[tg * K_ + tg1] * (float)mb[t + 1]
                   + eb[(size_t)t * K_ + tg] * (float)mb[t];
            }
        }
        sf[tid] = s; si[tid] = msum;
        __syncthreads();
        for (int off = 64; off > 0; off >>= 1) {
            if (tid < off) { sf[tid] += sf[tid + off]; si[tid] += si[tid + off]; }
            __syncthreads();
        }
        if (tid == 0) {
            int last_idx = si[0] - 1;
            if (last_idx < 0)   last_idx = 0;
            if (last_idx >= T_) last_idx = T_ - 1;
            const int lt = tb[last_idx] & (K_ - 1);
            g_num[b] = sf[0]
                     + eb[(size_t)(T_ - 1) * K_ + lt] * (float)mb[T_ - 1];
            __threadfence();
        }
    }

    // ---------------- completion ticket + final reduction ----------------
    __syncthreads();
    if (tid == 0) s_rank = atomicAdd(&g_count, 1u);
    __syncthreads();
    if (s_rank == NBLOCKS_ - 1) {              // last block
        __threadfence();
        sf[tid] = (g_num[tid] - g_denom[tid])
                + (g_num[tid + 128] - g_denom[tid + 128]);
        __syncthreads();
        for (int off = 64; off > 0; off >>= 1) {
            if (tid < off) sf[tid] += sf[tid + off];
            __syncthreads();
        }
        if (tid == 0) {
            out[0] = sf[0];
            g_count = 0;                       // reset for graph replay
        }
    }
}

// ---------------------------------------------------------------------------
extern "C" void kernel_launch(void* const* d_in, const int* in_sizes, int n_in,
                              void* d_out, int out_size) {
    const float* inp   = (const float*)d_in[0];   // (B,T,K) f32
    const float* trans = (const float*)d_in[1];   // (K,K)   f32
    const int*   tags  = (const int*)d_in[2];     // (B,T)   i32
    const int*   mask  = (const int*)d_in[3];     // (B,T)   i32
    float* out = (float*)d_out;

    fused_kernel<<<NBLOCKS_, 128>>>(inp, trans, tags, mask, out);
}

// round 17
// speedup vs baseline: 2.5968x; 2.5968x over previous
#include <cuda_runtime.h>

#define B_ 256
#define T_ 1024
#define K_ 128

__device__ float g_denom[B_];
__device__ float g_num[B_];

typedef unsigned long long u64;

__device__ __forceinline__ void ffma2(u64 &d, u64 a, u64 b) {
    asm("fma.rn.f32x2 %0, %1, %2, %0;" : "+l"(d) : "l"(a), "l"(b));
}
__device__ __forceinline__ u64 fadd2(u64 a, u64 b) {
    u64 r; asm("add.rn.f32x2 %0, %1, %2;" : "=l"(r) : "l"(a), "l"(b)); return r;
}
__device__ __forceinline__ u64 pack2(float lo, float hi) {
    u64 r; asm("mov.b64 %0, {%1, %2};" : "=l"(r) : "f"(lo), "f"(hi)); return r;
}
__device__ __forceinline__ void unpack2(u64 v, float &lo, float &hi) {
    asm("mov.b64 {%0, %1}, %2;" : "=f"(lo), "=f"(hi) : "l"(v));
}

// ---------------------------------------------------------------------------
// Champion configuration (R12 = 378.9us) + smask padding. The R16 NaN was a
// stray debug store to pbuf[0][0][0] racing group 0's init — removed.
//
// Fused forward + numerator launch:
//   blocks [0,128):   forward, 2 batches/block (2 groups x 128 threads,
//                     per-group named barriers -> phase-decoupled recurrences)
//   blocks [128,384): numerator, 1 batch/block
// Forward group: thread owns states jA / jA+64 and i-half h; permuted p
// layout -> 1-wavefront broadcast LDS.128; halves combine via one packed
// shfl_xor(16). Per-thread parallel rcp(p0) (concurrent with FMA tree),
// log(p0) off-path. 4-deep emission register ring hides DRAM latency.
// ---------------------------------------------------------------------------
__global__ void __launch_bounds__(256, 1) fused_kernel(
    const float* inp, const float* trans, const int* tags, const int* mask) {
    const int tid = threadIdx.x;

    __shared__ __align__(16) float pbuf[2][2][K_];   // [group][buffer][slot]
    __shared__ int smask[2][T_ + 8];                 // padded: clamp-free read
    __shared__ float sf[256];
    __shared__ int   si[256];

    if (blockIdx.x < 128) {
        // ================= forward =================
        const int g    = tid >> 7;            // group 0/1
        const int t128 = tid & 127;
        const int w    = t128 >> 5;           // warp-in-group 0..3
        const int l    = t128 & 31;
        const int h    = l >> 4;              // i-half
        const int jlo  = w * 16 + (l & 15);   // 0..63
        const int jA = jlo, jB = jlo + 64;
        const int b  = blockIdx.x * 2 + g;
        // permuted store slot: j=4q+r -> slot 4*(2*(q&15)+(q>>4)) + r
        const int posA = ((jlo >> 2) << 3) | (jlo & 3);   // posB = posA + 4

        for (int t = t128; t < T_; t += 128)
            smask[g][t] = mask[(size_t)b * T_ + t];
        if (t128 < 8) smask[g][T_ + t128] = 0;           // padding

        // E columns jA/jB for my i-half, packed pairs matching quad order.
        u64 EA[32], EB[32];
#pragma unroll
        for (int m = 0; m < 32; m++) {
            const int i = (h << 6) + 2 * m;
            EA[m] = pack2(__expf(trans[i * K_ + jA]),
                          __expf(trans[(i + 1) * K_ + jA]));
            EB[m] = pack2(__expf(trans[i * K_ + jB]),
                          __expf(trans[(i + 1) * K_ + jB]));
        }

        const float* ebA = inp + (size_t)b * T_ * K_ + jA;
        const float* ebB = inp + (size_t)b * T_ * K_ + jB;

        float pcA = __expf(ebA[0]);           // t = 0
        float pcB = __expf(ebB[0]);
        if (h == 0) { pbuf[g][0][posA] = pcA; pbuf[g][0][posA + 4] = pcB; }
        float C = 0.0f;

        // dual emission rings: ee = exp(emit[t]); r1..r4 raw emit[t+1..t+4]
        float eeA = __expf(ebA[K_]),      eeB = __expf(ebB[K_]);
        float r1A = ebA[2 * K_], r1B = ebB[2 * K_];
        float r2A = ebA[3 * K_], r2B = ebB[3 * K_];
        float r3A = ebA[4 * K_], r3B = ebB[4 * K_];
        float r4A = ebA[5 * K_], r4B = ebB[5 * K_];
        __syncthreads();                      // covers smask + pbuf init
        int mnext = smask[g][1];

        const int bar_id = g + 1;
        int cur = 0;
#pragma unroll 2
        for (int t = 1; t < T_; t++) {
            const int i5 = (t + 5 < T_) ? (t + 5) : (T_ - 1);   // clamped
            const float rnA = ebA[(size_t)i5 << 7];
            const float rnB = ebB[(size_t)i5 << 7];
            const float eA2 = __expf(r1A);    // exp(emit[t+1]), aged 4 steps
            const float eB2 = __expf(r1B);
            const int   mc  = mnext;
            mnext = smask[g][t + 1];          // padded: no clamp

            const float p0  = pbuf[g][cur][0];     // slot 0 == state 0
            const float rp0 = __frcp_rn(p0);       // || with FMA tree
            const float lp0 = __logf(p0);          // off-path (C only)

            const ulonglong2* pvh =
                (const ulonglong2*)pbuf[g][cur] + h;   // +16B for half 1
            u64 aA0 = 0ULL, aA1 = 0ULL, aA2 = 0ULL, aA3 = 0ULL;
            u64 aB0 = 0ULL, aB1 = 0ULL, aB2 = 0ULL, aB3 = 0ULL;
#pragma unroll
            for (int k = 0; k < 16; k += 2) {
                const ulonglong2 u = pvh[2 * k];          // p[64h+4k..+3]
                ffma2(aA0, u.x, EA[2 * k]);     ffma2(aA1, u.y, EA[2 * k + 1]);
                ffma2(aB0, u.x, EB[2 * k]);     ffma2(aB1, u.y, EB[2 * k + 1]);
                const ulonglong2 v = pvh[2 * k + 2];      // next quad
                ffma2(aA2, v.x, EA[2 * k + 2]); ffma2(aA3, v.y, EA[2 * k + 3]);
                ffma2(aB2, v.x, EB[2 * k + 2]); ffma2(aB3, v.y, EB[2 * k + 3]);
            }
            const u64 rA = fadd2(fadd2(aA0, aA1), fadd2(aA2, aA3));
            const u64 rB = fadd2(fadd2(aB0, aB1), fadd2(aB2, aB3));
            float loA, hiA, loB, hiB;
            unpack2(rA, loA, hiA);
            unpack2(rB, loB, hiB);
            // pack (hA, hB): one 64-bit butterfly + one packed add
            u64 hAB = pack2(loA + hiA, loB + hiB);
            const u64 oAB = __shfl_xor_sync(0xffffffffu, hAB, 16);
            float sA, sB; unpack2(fadd2(hAB, oAB), sA, sB);

            const float pnA = sA * (eeA * rp0);
            const float pnB = sB * (eeB * rp0);
            const float pwA = mc ? pnA : pcA;
            const float pwB = mc ? pnB : pcB;
            C += mc ? lp0 : 0.0f;

            cur ^= 1;
            if (h == 0) {
                pbuf[g][cur][posA]     = pwA;
                pbuf[g][cur][posA + 4] = pwB;
            }
            pcA = pwA; pcB = pwB;
            asm volatile("bar.sync %0, 128;" :: "r"(bar_id) : "memory");

            eeA = eA2; eeB = eB2;             // rotate rings
            r1A = r2A; r2A = r3A; r3A = r4A; r4A = rnA;
            r1B = r2B; r2B = r3B; r3B = r4B; r4B = rnB;
        }

        if (t128 == 0) {
            float sum = 0.0f;                 // fixed (permuted) order: determ.
            for (int i = 0; i < K_; i++) sum += pbuf[g][cur][i];
            g_denom[b] = C + __logf(sum);
        }
    } else {
        // ================= numerator =================
        const int b = blockIdx.x - 128;       // 0..255
        const int*   tb = tags + (size_t)b * T_;
        const int*   mb = mask + (size_t)b * T_;
        const float* eb = inp  + (size_t)b * T_ * K_;

        float s = 0.0f;
        int msum = 0;
        for (int t = tid; t < T_; t += 256) {
            msum += mb[t];
            if (t < T_ - 1) {
                const int tg  = tb[t]     & (K_ - 1);
                const int tg1 = tb[t + 1] & (K_ - 1);
                s += trans[tg * K_ + tg1] * (float)mb[t + 1]
                   + eb[(size_t)t * K_ + tg] * (float)mb[t];
            }
        }
        sf[tid] = s; si[tid] = msum;
        __syncthreads();
        for (int off = 128; off > 0; off >>= 1) {
            if (tid < off) { sf[tid] += sf[tid + off]; si[tid] += si[tid + off]; }
            __syncthreads();
        }
        if (tid == 0) {
            int last_idx = si[0] - 1;
            if (last_idx < 0)   last_idx = 0;
            if (last_idx >= T_) last_idx = T_ - 1;
            const int lt = tb[last_idx] & (K_ - 1);
            g_num[b] = sf[0]
                     + eb[(size_t)(T_ - 1) * K_ + lt] * (float)mb[T_ - 1];
        }
    }
}

// ---------------------------------------------------------------------------
__global__ void final_kernel(float* out) {
    __shared__ float sd[B_];
    const int t = threadIdx.x;
    sd[t] = g_num[t] - g_denom[t];
    __syncthreads();
    for (int off = 128; off > 0; off >>= 1) {
        if (t < off) sd[t] += sd[t + off];
        __syncthreads();
    }
    if (t == 0) out[0] = sd[0];
}

// ---------------------------------------------------------------------------
extern "C" void kernel_launch(void* const* d_in, const int* in_sizes, int n_in,
                              void* d_out, int out_size) {
    const float* inp   = (const float*)d_in[0];   // (B,T,K) f32
    const float* trans = (const float*)d_in[1];   // (K,K)   f32
    const int*   tags  = (const int*)d_in[2];     // (B,T)   i32
    const int*   mask  = (const int*)d_in[3];     // (B,T)   i32
    float* out = (float*)d_out;

    fused_kernel<<<128 + B_, 256>>>(inp, trans, tags, mask);
    final_kernel<<<1, B_>>>(out);
}